// round 5
// baseline (speedup 1.0000x reference)
#include <cuda_runtime.h>
#include <cstdint>

// Problem constants
#define P_     4096
#define B_     32
#define FEAT_  512
#define ATTN_  512
#define NH_    8
#define HD_    64
#define NROWS  (P_ * B_)          // 131072 rows of X (p,b)
#define CTX_N  (B_ * ATTN_)       // context floats (output offset for weight)
#define NCHUNK 32                 // P chunks for pass C
#define PCH    (P_ / NCHUNK)      // 128 pixels per chunk

// ---- device scratch (static: allocation-free rule) ----
__device__ float g_M[FEAT_ * ATTN_];                    // folded weight [f][col], pre-rounded tf32
__device__ float g_c[B_ * ATTN_];                       // per-batch bias [b][col]
__device__ float g_scores[B_ * NH_ * P_];               // [b*8+h][p]
__device__ float g_m[B_ * NH_];
__device__ float g_l[B_ * NH_];
__device__ float g_ypart[NCHUNK * B_ * NH_ * FEAT_];    // deterministic partial sums

// ============================================================
// helpers
// ============================================================
__device__ __forceinline__ uint32_t smem_u32(const void* p) {
    uint32_t a;
    asm("{ .reg .u64 t; cvta.to.shared.u64 t, %1; cvt.u32.u64 %0, t; }" : "=r"(a) : "l"(p));
    return a;
}
__device__ __forceinline__ uint32_t f2tf32(float x) {
    uint32_t r;
    asm("cvt.rna.tf32.f32 %0, %1;" : "=r"(r) : "f"(x));
    return r;
}
#define CP_ASYNC16(dst, src)  asm volatile("cp.async.cg.shared.global [%0], [%1], 16;" :: "r"(dst), "l"(src))
#define CP_COMMIT()           asm volatile("cp.async.commit_group;" ::: "memory")
#define CP_WAIT(n)            asm volatile("cp.async.wait_group %0;" :: "n"(n) : "memory")

__device__ __forceinline__ void mma_tf32(float* d, const uint32_t* a, const uint32_t* b) {
    asm volatile(
        "mma.sync.aligned.m16n8k8.row.col.f32.tf32.tf32.f32 "
        "{%0,%1,%2,%3}, {%4,%5,%6,%7}, {%8,%9}, {%0,%1,%2,%3};"
        : "+f"(d[0]), "+f"(d[1]), "+f"(d[2]), "+f"(d[3])
        : "r"(a[0]), "r"(a[1]), "r"(a[2]), "r"(a[3]), "r"(b[0]), "r"(b[1]));
}

// ============================================================
// prep_c: hid = last_hidden @ Ua_w + Ua_b;  then
// c[b,col] = (Wa_b_h @ Wa2)[j] + Wa2_b[j] + (hid_bh @ Ua2)[j] + Ua2_b[j]
// ============================================================
__global__ void prep_c(const float* __restrict__ lh,  const float* __restrict__ Ua_w,
                       const float* __restrict__ Ua_b, const float* __restrict__ Wa_b,
                       const float* __restrict__ Wa2_w, const float* __restrict__ Wa2_b,
                       const float* __restrict__ Ua2_w, const float* __restrict__ Ua2_b) {
    __shared__ float hid[ATTN_];
    int b = blockIdx.x, col = threadIdx.x;
    float acc = Ua_b[col];
    for (int f = 0; f < FEAT_; f++) acc += lh[b * FEAT_ + f] * Ua_w[f * ATTN_ + col];
    hid[col] = acc;
    __syncthreads();
    int h = col >> 6, j = col & 63;
    float c = Wa2_b[j] + Ua2_b[j];
    for (int k = 0; k < HD_; k++) {
        c += hid[h * HD_ + k] * Ua2_w[k * HD_ + j];
        c += Wa_b[h * HD_ + k] * Wa2_w[k * HD_ + j];
    }
    g_c[b * ATTN_ + col] = c;
}

// ============================================================
// prep_M: M[f, h*64+j] = sum_k Wa_w[f, h*64+k] * Wa2_w[k, j]
// pre-rounded to tf32 (rna) for unbiased HMMA input
// ============================================================
__global__ void prep_M(const float* __restrict__ Wa_w, const float* __restrict__ Wa2_w) {
    __shared__ float wrow[ATTN_];
    int f = blockIdx.x, col = threadIdx.x;
    wrow[col] = Wa_w[f * ATTN_ + col];
    __syncthreads();
    int h = col >> 6, j = col & 63;
    float acc = 0.f;
    for (int k = 0; k < HD_; k++) acc += wrow[h * HD_ + k] * Wa2_w[k * HD_ + j];
    g_M[f * ATTN_ + col] = __uint_as_float(f2tf32(acc));
}

// ============================================================
// passA_mma: T = X @ M via mma.sync tf32; fused tanh + va-dot -> scores
// CTA: BM=128 x BN=128 (2 heads) x K=512, BK=32 double-buffered cp.async.
// 8 warps: warp grid 4(M) x 2(N); warp tile 32x64 (one head per warp).
// Shared strides: Xs stride 36 fl, Ms stride 136 fl -> conflict-free frags.
// ============================================================
#define BK     32
#define NKT    (FEAT_ / BK)         // 16 chunks
#define XS_STRIDE 36                // floats; 36 % 32 = 4 -> conflict-free A frags
#define MS_STRIDE 136               // floats; 136 % 32 = 8 -> conflict-free B frags
// dynamic smem layout (floats)
#define OFF_X0  0
#define OFF_X1  (128 * XS_STRIDE)                 // 4608
#define OFF_M0  (2 * 128 * XS_STRIDE)             // 9216
#define OFF_M1  (OFF_M0 + BK * MS_STRIDE)         // 13568
#define OFF_VA  (OFF_M0 + 2 * BK * MS_STRIDE)     // 17920
#define SMEM_FL (OFF_VA + 64)                     // 17984 floats
#define SMEM_TOT (SMEM_FL * 4)                    // 71936 bytes

__global__ void __launch_bounds__(256, 2) passA_mma(const float* __restrict__ X,
                                                    const float* __restrict__ va_w,
                                                    const float* __restrict__ va_b) {
    extern __shared__ float smf[];
    const uint32_t sbase = smem_u32(smf);
    const int tid = threadIdx.x;
    const int wid = tid >> 5, lane = tid & 31;
    const int q = lane >> 2, r = lane & 3;      // quad row / quad lane
    const int warp_m = wid & 3, warp_n = wid >> 2;
    const int nbase = blockIdx.x * 128;
    const int rowbase = blockIdx.y * 128;
    const int head = (nbase >> 6) + warp_n;

    if (tid < 64) smf[OFF_VA + tid] = va_w[tid];

    // ---- chunk loader: X 1024 f4 + M 1024 f4, 8 cp.async per thread ----
    auto load_chunk = [&](int kt, int bf) {
        int k0 = kt * BK;
        uint32_t xb = sbase + (bf ? OFF_X1 : OFF_X0) * 4;
        uint32_t mb = sbase + (bf ? OFF_M1 : OFF_M0) * 4;
#pragma unroll
        for (int t = 0; t < 4; t++) {
            int g = tid + t * 256;
            int row = g >> 3, qq = g & 7;       // 8 float4 per 32-float row
            uint32_t dst = xb + row * (XS_STRIDE * 4) + qq * 16;
            const float* src = X + (size_t)(rowbase + row) * FEAT_ + k0 + qq * 4;
            CP_ASYNC16(dst, src);
        }
#pragma unroll
        for (int t = 0; t < 4; t++) {
            int g = tid + t * 256;
            int k = g >> 5, qq = g & 31;        // 32 float4 per 128-float row
            uint32_t dst = mb + k * (MS_STRIDE * 4) + qq * 16;
            const float* src = g_M + (size_t)(k0 + k) * ATTN_ + nbase + qq * 4;
            CP_ASYNC16(dst, src);
        }
        CP_COMMIT();
    };

    float acc[2][8][4];
#pragma unroll
    for (int mt = 0; mt < 2; mt++)
#pragma unroll
        for (int nt = 0; nt < 8; nt++)
#pragma unroll
            for (int e = 0; e < 4; e++) acc[mt][nt][e] = 0.f;

    load_chunk(0, 0);

    for (int kt = 0; kt < NKT; kt++) {
        int bf = kt & 1;
        __syncthreads();                        // prior compute done before overwrite
        if (kt < NKT - 1) {
            load_chunk(kt + 1, bf ^ 1);
            CP_WAIT(1);                         // chunk kt landed
        } else {
            CP_WAIT(0);
        }
        __syncthreads();

        const float* xs = smf + (bf ? OFF_X1 : OFF_X0);
        const float* ms = smf + (bf ? OFF_M1 : OFF_M0);
#pragma unroll
        for (int kk = 0; kk < 4; kk++) {
            int k0 = kk * 8;
            uint32_t afr[2][4];
#pragma unroll
            for (int mt = 0; mt < 2; mt++) {
                int row = warp_m * 32 + mt * 16 + q;
                afr[mt][0] = f2tf32(xs[row * XS_STRIDE + k0 + r]);
                afr[mt][1] = f2tf32(xs[(row + 8) * XS_STRIDE + k0 + r]);
                afr[mt][2] = f2tf32(xs[row * XS_STRIDE + k0 + r + 4]);
                afr[mt][3] = f2tf32(xs[(row + 8) * XS_STRIDE + k0 + r + 4]);
            }
            uint32_t bfr[8][2];
#pragma unroll
            for (int nt = 0; nt < 8; nt++) {
                int n = warp_n * 64 + nt * 8 + q;
                bfr[nt][0] = __float_as_uint(ms[(k0 + r) * MS_STRIDE + n]);
                bfr[nt][1] = __float_as_uint(ms[(k0 + r + 4) * MS_STRIDE + n]);
            }
#pragma unroll
            for (int mt = 0; mt < 2; mt++)
#pragma unroll
                for (int nt = 0; nt < 8; nt++)
                    mma_tf32(acc[mt][nt], afr[mt], bfr[nt]);
        }
    }

    // ---- epilogue: tanh + va-dot, quad reduction, score write ----
    float vb = va_b[0];
    const float* va_s = smf + OFF_VA;
#pragma unroll
    for (int mt = 0; mt < 2; mt++) {
#pragma unroll
        for (int ro = 0; ro < 2; ro++) {
            int rglob = rowbase + warp_m * 32 + mt * 16 + q + ro * 8;
            int b = rglob & (B_ - 1), p = rglob >> 5;
            const float* crow = &g_c[b * ATTN_ + head * HD_];
            float s = 0.f;
#pragma unroll
            for (int nt = 0; nt < 8; nt++) {
                int col = nt * 8 + r * 2;
                float2 cc = *reinterpret_cast<const float2*>(&crow[col]);
                s += tanhf(acc[mt][nt][ro * 2 + 0] + cc.x) * va_s[col];
                s += tanhf(acc[mt][nt][ro * 2 + 1] + cc.y) * va_s[col + 1];
            }
            s += __shfl_xor_sync(0xffffffffu, s, 1, 4);
            s += __shfl_xor_sync(0xffffffffu, s, 2, 4);
            if (r == 0) g_scores[(b * NH_ + head) * P_ + p] = s + vb;
        }
    }
}

// ============================================================
// passB: softmax stats (max, sum-exp) over P per (b,h)
// ============================================================
__global__ void passB() {
    int bh = blockIdx.x;
    const float* s = &g_scores[bh * P_];
    __shared__ float red[256];
    int tid = threadIdx.x;
    float m = -1e30f;
    for (int i = tid; i < P_; i += 256) m = fmaxf(m, s[i]);
    red[tid] = m; __syncthreads();
    for (int st = 128; st > 0; st >>= 1) {
        if (tid < st) red[tid] = fmaxf(red[tid], red[tid + st]);
        __syncthreads();
    }
    m = red[0]; __syncthreads();
    float l = 0.f;
    for (int i = tid; i < P_; i += 256) l += expf(s[i] - m);
    red[tid] = l; __syncthreads();
    for (int st = 128; st > 0; st >>= 1) {
        if (tid < st) red[tid] += red[tid + st];
        __syncthreads();
    }
    if (tid == 0) { g_m[bh] = m; g_l[bh] = red[0]; }
}

// ============================================================
// passC: per (chunk, b): w = exp(s-m)/l; writes weight output;
// partial y_{b,h} += sum_p w * x_pb (deterministic per-chunk partials)
// ============================================================
__global__ __launch_bounds__(256) void passC(const float* __restrict__ X, float* __restrict__ out) {
    int chunk = blockIdx.x, b = blockIdx.y;
    int p0 = chunk * PCH;
    int tid = threadIdx.x;
    __shared__ float m_s[NH_], li_s[NH_];
    __shared__ float w_s[PCH * NH_];   // [p_local][h]
    if (tid < NH_) { m_s[tid] = g_m[b * NH_ + tid]; li_s[tid] = 1.f / g_l[b * NH_ + tid]; }
    __syncthreads();
    for (int idx = tid; idx < PCH * NH_; idx += 256) {
        int pl = idx >> 3, h = idx & 7;
        float s = g_scores[(b * NH_ + h) * P_ + p0 + pl];
        w_s[idx] = expf(s - m_s[h]) * li_s[h];
    }
    __syncthreads();
    // weight output = mean over heads
    if (tid < PCH) {
        float sum = 0.f;
#pragma unroll
        for (int h = 0; h < NH_; h++) sum += w_s[tid * NH_ + h];
        out[CTX_N + (p0 + tid) * B_ + b] = sum * (1.0f / NH_);
    }
    // weighted reduction of X rows; each thread owns cols tid and tid+256
    float acc[NH_][2];
#pragma unroll
    for (int h = 0; h < NH_; h++) { acc[h][0] = 0.f; acc[h][1] = 0.f; }
    for (int pl = 0; pl < PCH; pl++) {
        const float* xr = &X[(size_t)((p0 + pl) * B_ + b) * FEAT_];
        float x0 = xr[tid], x1 = xr[tid + 256];
#pragma unroll
        for (int h = 0; h < NH_; h++) {
            float w = w_s[pl * NH_ + h];
            acc[h][0] += w * x0;
            acc[h][1] += w * x1;
        }
    }
    float* yp = &g_ypart[(size_t)chunk * (B_ * NH_ * FEAT_) + (b * NH_) * FEAT_];
#pragma unroll
    for (int h = 0; h < NH_; h++) {
        yp[h * FEAT_ + tid]       = acc[h][0];
        yp[h * FEAT_ + tid + 256] = acc[h][1];
    }
}

// ============================================================
// passD: y = sum over chunks of partials; context = y @ Wa_w(head slice) + Wa_b
// ============================================================
__global__ void passD(const float* __restrict__ Wa_w, const float* __restrict__ Wa_b,
                      float* __restrict__ out) {
    int b = blockIdx.x, col = threadIdx.x;
    __shared__ float y_s[NH_ * FEAT_];
    for (int idx = col; idx < NH_ * FEAT_; idx += 512) {
        float acc = 0.f;
        for (int ch = 0; ch < NCHUNK; ch++)
            acc += g_ypart[(size_t)ch * (B_ * NH_ * FEAT_) + b * (NH_ * FEAT_) + idx];
        y_s[idx] = acc;
    }
    __syncthreads();
    int h = col >> 6;
    float acc = Wa_b[col];
    const float* yrow = &y_s[h * FEAT_];
    for (int f = 0; f < FEAT_; f++) acc += yrow[f] * Wa_w[f * ATTN_ + col];
    out[b * ATTN_ + col] = acc;
}

// ============================================================
extern "C" void kernel_launch(void* const* d_in, const int* in_sizes, int n_in,
                              void* d_out, int out_size) {
    (void)in_sizes; (void)n_in; (void)out_size;
    const float* lh    = (const float*)d_in[0];   // last_hidden   [1,B,512]
    const float* X     = (const float*)d_in[1];   // encoder_outputs [P,B,512]
    const float* Wa_w  = (const float*)d_in[2];
    const float* Wa_b  = (const float*)d_in[3];
    const float* Ua_w  = (const float*)d_in[4];
    const float* Ua_b  = (const float*)d_in[5];
    const float* Wa2_w = (const float*)d_in[6];
    const float* Wa2_b = (const float*)d_in[7];
    const float* Ua2_w = (const float*)d_in[8];
    const float* Ua2_b = (const float*)d_in[9];
    const float* va_w  = (const float*)d_in[10];
    const float* va_b  = (const float*)d_in[11];
    float* out = (float*)d_out;

    cudaFuncSetAttribute(passA_mma, cudaFuncAttributeMaxDynamicSharedMemorySize, SMEM_TOT);

    prep_c<<<B_, ATTN_>>>(lh, Ua_w, Ua_b, Wa_b, Wa2_w, Wa2_b, Ua2_w, Ua2_b);
    prep_M<<<FEAT_, ATTN_>>>(Wa_w, Wa2_w);
    passA_mma<<<dim3(ATTN_ / 128, NROWS / 128), 256, SMEM_TOT>>>(X, va_w, va_b);
    passB<<<B_ * NH_, 256>>>();
    passC<<<dim3(NCHUNK, B_), 256>>>(X, out);
    passD<<<B_, ATTN_>>>(Wa_w, Wa_b, out);
}

// round 7
// speedup vs baseline: 1.3827x; 1.3827x over previous
#include <cuda_runtime.h>
#include <cuda_fp16.h>
#include <cstdint>

// Problem constants
#define P_     4096
#define B_     32
#define FEAT_  512
#define ATTN_  512
#define NH_    8
#define HD_    64
#define NROWS  (P_ * B_)          // 131072 rows of X (p,b)
#define CTX_N  (B_ * ATTN_)       // context floats (output offset for weight)
#define NCHUNK 32                 // P chunks for pass C
#define PCH    (P_ / NCHUNK)      // 128 pixels per chunk

// ---- device scratch (static: allocation-free rule) ----
__device__ __half g_Mh[ATTN_ * FEAT_];                  // folded weight fp16, K-major [col][f]
__device__ float g_c[B_ * ATTN_];                       // per-batch bias [b][col]
__device__ float g_scores[B_ * NH_ * P_];               // [b*8+h][p]
__device__ float g_m[B_ * NH_];
__device__ float g_l[B_ * NH_];
__device__ float g_ypart[NCHUNK * B_ * NH_ * FEAT_];    // deterministic partial sums

// ============================================================
// helpers
// ============================================================
__device__ __forceinline__ uint32_t smem_u32(const void* p) {
    uint32_t a;
    asm("{ .reg .u64 t; cvta.to.shared.u64 t, %1; cvt.u32.u64 %0, t; }" : "=r"(a) : "l"(p));
    return a;
}
__device__ __forceinline__ uint32_t pack_h2(float lo, float hi) {
    uint32_t r;   // cvt.rn.f16x2.f32 d, a, b : a -> high half, b -> low half
    asm("cvt.rn.f16x2.f32 %0, %1, %2;" : "=r"(r) : "f"(hi), "f"(lo));
    return r;
}
__device__ __forceinline__ float tanha(float x) {
    float r;
    asm("tanh.approx.f32 %0, %1;" : "=f"(r) : "f"(x));
    return r;
}
#define CP_ASYNC16(dst, src)  asm volatile("cp.async.cg.shared.global [%0], [%1], 16;" :: "r"(dst), "l"(src))
#define CP_COMMIT()           asm volatile("cp.async.commit_group;" ::: "memory")
#define CP_WAIT(n)            asm volatile("cp.async.wait_group %0;" :: "n"(n) : "memory")

// fp16 MMA m16n8k16, fp32 accumulate
__device__ __forceinline__ void mma_f16(float* d, const uint32_t* a, const uint32_t* b) {
    asm volatile(
        "mma.sync.aligned.m16n8k16.row.col.f32.f16.f16.f32 "
        "{%0,%1,%2,%3}, {%4,%5,%6,%7}, {%8,%9}, {%0,%1,%2,%3};"
        : "+f"(d[0]), "+f"(d[1]), "+f"(d[2]), "+f"(d[3])
        : "r"(a[0]), "r"(a[1]), "r"(a[2]), "r"(a[3]), "r"(b[0]), "r"(b[1]));
}

// ============================================================
// prep_c: hid = last_hidden @ Ua_w + Ua_b;  then
// c[b,col] = (Wa_b_h @ Wa2)[j] + Wa2_b[j] + (hid_bh @ Ua2)[j] + Ua2_b[j]
// ============================================================
__global__ void prep_c(const float* __restrict__ lh,  const float* __restrict__ Ua_w,
                       const float* __restrict__ Ua_b, const float* __restrict__ Wa_b,
                       const float* __restrict__ Wa2_w, const float* __restrict__ Wa2_b,
                       const float* __restrict__ Ua2_w, const float* __restrict__ Ua2_b) {
    __shared__ float hid[ATTN_];
    int b = blockIdx.x, col = threadIdx.x;
    float acc = Ua_b[col];
    for (int f = 0; f < FEAT_; f++) acc += lh[b * FEAT_ + f] * Ua_w[f * ATTN_ + col];
    hid[col] = acc;
    __syncthreads();
    int h = col >> 6, j = col & 63;
    float c = Wa2_b[j] + Ua2_b[j];
    for (int k = 0; k < HD_; k++) {
        c += hid[h * HD_ + k] * Ua2_w[k * HD_ + j];
        c += Wa_b[h * HD_ + k] * Wa2_w[k * HD_ + j];
    }
    g_c[b * ATTN_ + col] = c;
}

// ============================================================
// prep_M: M[f, h*64+j] = sum_k Wa_w[f, h*64+k] * Wa2_w[k, j]
// stored as fp16, K-major: g_Mh[col * 512 + f]
// ============================================================
__global__ void prep_M(const float* __restrict__ Wa_w, const float* __restrict__ Wa2_w) {
    __shared__ float wrow[ATTN_];
    int f = blockIdx.x, col = threadIdx.x;
    wrow[col] = Wa_w[f * ATTN_ + col];
    __syncthreads();
    int h = col >> 6, j = col & 63;
    float acc = 0.f;
    for (int k = 0; k < HD_; k++) acc += wrow[h * HD_ + k] * Wa2_w[k * HD_ + j];
    g_Mh[col * FEAT_ + f] = __float2half_rn(acc);
}

// ============================================================
// passA_mma: T = X @ M via mma.sync fp16 m16n8k16; tanh + va-dot -> scores
// CTA: BM=128 x BN=128 (2 heads), BK=32, double-buffered cp.async, occ 2.
// 8 warps: 4(M) x 2(N); warp tile 32x64.
// Xs: fp32, stride 40 floats (conflict-free LDS.64 A-frags)
// Ms: fp16 K-major [n][k], stride 56 halves (conflict-free half2 B-frags)
// ============================================================
#define BK     32
#define NKT    (FEAT_ / BK)          // 16 chunks
#define XS_STRIDE 40                 // floats per row
#define MS_STRIDE 56                 // halves per row
// byte offsets in dynamic smem
#define OFF_X0  0
#define OFF_X1  (128 * XS_STRIDE * 4)              // 20480
#define OFF_M0  (2 * 128 * XS_STRIDE * 4)          // 40960
#define OFF_M1  (OFF_M0 + 128 * MS_STRIDE * 2)     // 55296
#define OFF_VA  (OFF_M0 + 2 * 128 * MS_STRIDE * 2) // 69632
#define SMEM_TOT (OFF_VA + 256)                    // 69888 bytes

__global__ void __launch_bounds__(256, 2) passA_mma(const float* __restrict__ X,
                                                    const float* __restrict__ va_w,
                                                    const float* __restrict__ va_b) {
    extern __shared__ char smc[];
    float* smf = (float*)smc;
    const uint32_t sbase = smem_u32(smc);
    const int tid = threadIdx.x;
    const int wid = tid >> 5, lane = tid & 31;
    const int q = lane >> 2, r = lane & 3;      // quad row / quad lane
    const int warp_m = wid & 3, warp_n = wid >> 2;
    const int nbase = blockIdx.x * 128;
    const int rowbase = blockIdx.y * 128;
    const int head = (nbase >> 6) + warp_n;

    if (tid < 64) ((float*)(smc + OFF_VA))[tid] = va_w[tid];

    // ---- chunk loader: X 1024x16B + M 512x16B => 6 cp.async / thread ----
    auto load_chunk = [&](int kt, int bf) {
        int k0 = kt * BK;
        uint32_t xb = sbase + (bf ? OFF_X1 : OFF_X0);
        uint32_t mb = sbase + (bf ? OFF_M1 : OFF_M0);
#pragma unroll
        for (int t = 0; t < 4; t++) {
            int g = tid + t * 256;
            int row = g >> 3, qq = g & 7;       // 8 x 16B per 32-float row
            uint32_t dst = xb + row * (XS_STRIDE * 4) + qq * 16;
            const float* src = X + (size_t)(rowbase + row) * FEAT_ + k0 + qq * 4;
            CP_ASYNC16(dst, src);
        }
#pragma unroll
        for (int t = 0; t < 2; t++) {
            int g = tid + t * 256;
            int n = g >> 2, qq = g & 3;         // 4 x 16B per 32-half row
            uint32_t dst = mb + n * (MS_STRIDE * 2) + qq * 16;
            const __half* src = g_Mh + (size_t)(nbase + n) * FEAT_ + k0 + qq * 8;
            CP_ASYNC16(dst, src);
        }
        CP_COMMIT();
    };

    float acc[2][8][4];
#pragma unroll
    for (int mt = 0; mt < 2; mt++)
#pragma unroll
        for (int nt = 0; nt < 8; nt++)
#pragma unroll
            for (int e = 0; e < 4; e++) acc[mt][nt][e] = 0.f;

    load_chunk(0, 0);

    for (int kt = 0; kt < NKT; kt++) {
        int bf = kt & 1;
        __syncthreads();                        // prior compute done before overwrite
        if (kt < NKT - 1) {
            load_chunk(kt + 1, bf ^ 1);
            CP_WAIT(1);                         // chunk kt landed
        } else {
            CP_WAIT(0);
        }
        __syncthreads();

        const float* xs = smf + (bf ? OFF_X1 : OFF_X0) / 4;
        const __half* ms = (const __half*)(smc + (bf ? OFF_M1 : OFF_M0));
#pragma unroll
        for (int kk = 0; kk < 2; kk++) {        // two k16 steps per 32-chunk
            int k0 = kk * 16;
            uint32_t afr[2][4];
#pragma unroll
            for (int mt = 0; mt < 2; mt++) {
                int row = warp_m * 32 + mt * 16 + q;
                float2 v0 = *reinterpret_cast<const float2*>(&xs[row * XS_STRIDE + k0 + r * 2]);
                float2 v1 = *reinterpret_cast<const float2*>(&xs[(row + 8) * XS_STRIDE + k0 + r * 2]);
                float2 v2 = *reinterpret_cast<const float2*>(&xs[row * XS_STRIDE + k0 + r * 2 + 8]);
                float2 v3 = *reinterpret_cast<const float2*>(&xs[(row + 8) * XS_STRIDE + k0 + r * 2 + 8]);
                afr[mt][0] = pack_h2(v0.x, v0.y);
                afr[mt][1] = pack_h2(v1.x, v1.y);
                afr[mt][2] = pack_h2(v2.x, v2.y);
                afr[mt][3] = pack_h2(v3.x, v3.y);
            }
            uint32_t bfr[8][2];
#pragma unroll
            for (int nt = 0; nt < 8; nt++) {
                int n = warp_n * 64 + nt * 8 + q;
                bfr[nt][0] = *reinterpret_cast<const uint32_t*>(&ms[n * MS_STRIDE + k0 + r * 2]);
                bfr[nt][1] = *reinterpret_cast<const uint32_t*>(&ms[n * MS_STRIDE + k0 + r * 2 + 8]);
            }
#pragma unroll
            for (int mt = 0; mt < 2; mt++)
#pragma unroll
                for (int nt = 0; nt < 8; nt++)
                    mma_f16(acc[mt][nt], afr[mt], bfr[nt]);
        }
    }

    // ---- epilogue: tanh + va-dot, quad reduction, score write ----
    float vb = va_b[0];
    const float* va_s = (const float*)(smc + OFF_VA);
#pragma unroll
    for (int mt = 0; mt < 2; mt++) {
#pragma unroll
        for (int ro = 0; ro < 2; ro++) {
            int rglob = rowbase + warp_m * 32 + mt * 16 + q + ro * 8;
            int b = rglob & (B_ - 1), p = rglob >> 5;
            const float* crow = &g_c[b * ATTN_ + head * HD_];
            float s = 0.f;
#pragma unroll
            for (int nt = 0; nt < 8; nt++) {
                int col = nt * 8 + r * 2;
                float2 cc = *reinterpret_cast<const float2*>(&crow[col]);
                s += tanha(acc[mt][nt][ro * 2 + 0] + cc.x) * va_s[col];
                s += tanha(acc[mt][nt][ro * 2 + 1] + cc.y) * va_s[col + 1];
            }
            s += __shfl_xor_sync(0xffffffffu, s, 1, 4);
            s += __shfl_xor_sync(0xffffffffu, s, 2, 4);
            if (r == 0) g_scores[(b * NH_ + head) * P_ + p] = s + vb;
        }
    }
}

// ============================================================
// passB: softmax stats (max, sum-exp) over P per (b,h)
// ============================================================
__global__ void passB() {
    int bh = blockIdx.x;
    const float* s = &g_scores[bh * P_];
    __shared__ float red[256];
    int tid = threadIdx.x;
    float m = -1e30f;
    for (int i = tid; i < P_; i += 256) m = fmaxf(m, s[i]);
    red[tid] = m; __syncthreads();
    for (int st = 128; st > 0; st >>= 1) {
        if (tid < st) red[tid] = fmaxf(red[tid], red[tid + st]);
        __syncthreads();
    }
    m = red[0]; __syncthreads();
    float l = 0.f;
    for (int i = tid; i < P_; i += 256) l += expf(s[i] - m);
    red[tid] = l; __syncthreads();
    for (int st = 128; st > 0; st >>= 1) {
        if (tid < st) red[tid] += red[tid + st];
        __syncthreads();
    }
    if (tid == 0) { g_m[bh] = m; g_l[bh] = red[0]; }
}

// ============================================================
// passC: per (chunk, b): w = exp(s-m)/l; writes weight output;
// partial y_{b,h} += sum_p w * x_pb (deterministic per-chunk partials)
// ============================================================
__global__ __launch_bounds__(256) void passC(const float* __restrict__ X, float* __restrict__ out) {
    int chunk = blockIdx.x, b = blockIdx.y;
    int p0 = chunk * PCH;
    int tid = threadIdx.x;
    __shared__ float m_s[NH_], li_s[NH_];
    __shared__ float w_s[PCH * NH_];   // [p_local][h]
    if (tid < NH_) { m_s[tid] = g_m[b * NH_ + tid]; li_s[tid] = 1.f / g_l[b * NH_ + tid]; }
    __syncthreads();
    for (int idx = tid; idx < PCH * NH_; idx += 256) {
        int pl = idx >> 3, h = idx & 7;
        float s = g_scores[(b * NH_ + h) * P_ + p0 + pl];
        w_s[idx] = expf(s - m_s[h]) * li_s[h];
    }
    __syncthreads();
    // weight output = mean over heads
    if (tid < PCH) {
        float sum = 0.f;
#pragma unroll
        for (int h = 0; h < NH_; h++) sum += w_s[tid * NH_ + h];
        out[CTX_N + (p0 + tid) * B_ + b] = sum * (1.0f / NH_);
    }
    // weighted reduction of X rows; each thread owns cols tid and tid+256
    float acc[NH_][2];
#pragma unroll
    for (int h = 0; h < NH_; h++) { acc[h][0] = 0.f; acc[h][1] = 0.f; }
#pragma unroll 4
    for (int pl = 0; pl < PCH; pl++) {
        const float* xr = &X[(size_t)((p0 + pl) * B_ + b) * FEAT_];
        float x0 = xr[tid], x1 = xr[tid + 256];
#pragma unroll
        for (int h = 0; h < NH_; h++) {
            float w = w_s[pl * NH_ + h];
            acc[h][0] += w * x0;
            acc[h][1] += w * x1;
        }
    }
    float* yp = &g_ypart[(size_t)chunk * (B_ * NH_ * FEAT_) + (b * NH_) * FEAT_];
#pragma unroll
    for (int h = 0; h < NH_; h++) {
        yp[h * FEAT_ + tid]       = acc[h][0];
        yp[h * FEAT_ + tid + 256] = acc[h][1];
    }
}

// ============================================================
// passD: y = sum over chunks of partials; context = y @ Wa_w(head slice) + Wa_b
// ============================================================
__global__ void passD(const float* __restrict__ Wa_w, const float* __restrict__ Wa_b,
                      float* __restrict__ out) {
    int b = blockIdx.x, col = threadIdx.x;
    __shared__ float y_s[NH_ * FEAT_];
    for (int idx = col; idx < NH_ * FEAT_; idx += 512) {
        float acc = 0.f;
        for (int ch = 0; ch < NCHUNK; ch++)
            acc += g_ypart[(size_t)ch * (B_ * NH_ * FEAT_) + b * (NH_ * FEAT_) + idx];
        y_s[idx] = acc;
    }
    __syncthreads();
    int h = col >> 6;
    float acc = Wa_b[col];
    const float* yrow = &y_s[h * FEAT_];
    for (int f = 0; f < FEAT_; f++) acc += yrow[f] * Wa_w[f * ATTN_ + col];
    out[b * ATTN_ + col] = acc;
}

// ============================================================
extern "C" void kernel_launch(void* const* d_in, const int* in_sizes, int n_in,
                              void* d_out, int out_size) {
    (void)in_sizes; (void)n_in; (void)out_size;
    const float* lh    = (const float*)d_in[0];   // last_hidden   [1,B,512]
    const float* X     = (const float*)d_in[1];   // encoder_outputs [P,B,512]
    const float* Wa_w  = (const float*)d_in[2];
    const float* Wa_b  = (const float*)d_in[3];
    const float* Ua_w  = (const float*)d_in[4];
    const float* Ua_b  = (const float*)d_in[5];
    const float* Wa2_w = (const float*)d_in[6];
    const float* Wa2_b = (const float*)d_in[7];
    const float* Ua2_w = (const float*)d_in[8];
    const float* Ua2_b = (const float*)d_in[9];
    const float* va_w  = (const float*)d_in[10];
    const float* va_b  = (const float*)d_in[11];
    float* out = (float*)d_out;

    cudaFuncSetAttribute(passA_mma, cudaFuncAttributeMaxDynamicSharedMemorySize, SMEM_TOT);

    prep_c<<<B_, ATTN_>>>(lh, Ua_w, Ua_b, Wa_b, Wa2_w, Wa2_b, Ua2_w, Ua2_b);
    prep_M<<<FEAT_, ATTN_>>>(Wa_w, Wa2_w);
    passA_mma<<<dim3(ATTN_ / 128, NROWS / 128), 256, SMEM_TOT>>>(X, va_w, va_b);
    passB<<<B_ * NH_, 256>>>();
    passC<<<dim3(NCHUNK, B_), 256>>>(X, out);
    passD<<<B_, ATTN_>>>(Wa_w, Wa_b, out);
}